// round 10
// baseline (speedup 1.0000x reference)
#include <cuda_runtime.h>
#include <cstdint>

// Problem constants
#define BB   4
#define TT   2048
#define NC   4096
#define AA   8
#define SINK_ITERS 20
#define EPS_ 1e-5f

#define TOK    16             // tokens per CTA
#define KSPLIT 8
#define DPART  (NC / KSPLIT)  // 512
#define PARTW  28             // partial row: 24 logits + ssq + pad
#define NTHR   256

// phi slice in smem: [24][512] floats, row = 2048 B (128B-aligned)
#define PHI_FLOATS (24 * DPART)    // 12288 floats = 48 KB

// ---------------- scratch ----------------
__device__ __align__(16) float g_buf[AA * 24 * NC];                 // folded phi TRANSPOSED [a][k][d]
__device__ __align__(16) float part_buf[KSPLIT * BB * TT * PARTW];  // 7.3 MB
__device__ __align__(16) float W_buf[BB * TT * 16];

// ---------------- helpers ----------------
typedef unsigned long long ull;
__device__ __forceinline__ void ffma2(ull& d, ull a, ull b) {
    asm("fma.rn.f32x2 %0, %1, %2, %0;" : "+l"(d) : "l"(a), "l"(b));
}
__device__ __forceinline__ void fadd2(ull& d, ull a, ull b) {
    asm("add.rn.f32x2 %0, %1, %2;" : "=l"(d) : "l"(a), "l"(b));
}
__device__ __forceinline__ void unpack2(ull u, float& lo, float& hi) {
    asm("mov.b64 {%0, %1}, %2;" : "=f"(lo), "=f"(hi) : "l"(u));
}
__device__ __forceinline__ void cp16(uint32_t dst, const void* src) {
    asm volatile("cp.async.cg.shared.global [%0], [%1], 16;" :: "r"(dst), "l"(src));
}

// ---------------- kernel 1: fold alpha*w*phi -> g_buf[a][k][d] (k-major / transposed) ----------------
__global__ void fold_k(const float* __restrict__ wnorm,
                       const float* __restrict__ ppre, const float* __restrict__ ppost,
                       const float* __restrict__ pres,
                       const float* __restrict__ apre, const float* __restrict__ apost,
                       const float* __restrict__ ares) {
    int ad = blockIdx.x * 128 + threadIdx.x;     // a*4096 + d
    if (ad >= AA * NC) return;
    int a = ad >> 12, d = ad & (NC - 1);
    float wv = wnorm[ad];
    float cp = apre[a] * wv, cq = apost[a] * wv, cr = ares[a] * wv;
    float* dst = g_buf + (size_t)a * 24 * NC + d;
    float4 v;
    v = ((const float4*)ppre)[ad];
    dst[0 * NC] = cp * v.x; dst[1 * NC] = cp * v.y; dst[2 * NC] = cp * v.z; dst[3 * NC] = cp * v.w;
    v = ((const float4*)ppost)[ad];
    dst[4 * NC] = cq * v.x; dst[5 * NC] = cq * v.y; dst[6 * NC] = cq * v.z; dst[7 * NC] = cq * v.w;
#pragma unroll
    for (int q = 0; q < 4; ++q) {
        v = ((const float4*)pres)[(size_t)ad * 4 + q];
        dst[(8 + 4 * q) * NC] = cr * v.x; dst[(9 + 4 * q) * NC] = cr * v.y;
        dst[(10 + 4 * q) * NC] = cr * v.z; dst[(11 + 4 * q) * NC] = cr * v.w;
    }
}

// ---------------- kernel 2: partial logits — streaming, one barrier ----------------
// grid = 4096: blockIdx.x = tt*KSPLIT + ks. 256 threads:
//   s = tid&7 (d-slice), slot = (tid>>3)&7, kh = tid>>6 (k quarter: 6 ks)
// Thread: tokens (t0+slot, t0+slot+8), ks kh*6..kh*6+5, d = j*32 + s*4 (+0..3), j=0..15.
// acc[tok*6+c] = f32x2 over genuine d-pairs -> reduce with lo+hi.
__global__ void __launch_bounds__(NTHR, 3)
logits_k(const float* __restrict__ x, const int* __restrict__ aidx) {
    __shared__ __align__(16) float sphi[PHI_FLOATS];   // [24][512], 48 KB

    const int tid = threadIdx.x;
    const int ks = blockIdx.x & (KSPLIT - 1);
    const int tt = blockIdx.x >> 3;              // token tile 0..511
    const int t0 = tt * TOK;
    const int aid = aidx[tt >> 7];               // 128 tiles per batch
    const int s = tid & 7, slot = (tid >> 3) & 7, kh = tid >> 6;

    // one-shot phi slice load: 3072 float4, 12 per thread, coalesced
    const float* gb = g_buf + (size_t)aid * 24 * NC + ks * DPART;
    uint32_t sb = (uint32_t)__cvta_generic_to_shared(sphi);
#pragma unroll
    for (int i = 0; i < 12; ++i) {
        int f = i * NTHR + tid;                  // 0..3071
        int k = f >> 7, c4 = f & 127;
        cp16(sb + (k * DPART + c4 * 4) * 4, gb + (size_t)k * NC + c4 * 4);
    }
    asm volatile("cp.async.commit_group;");

    const float* xA = x + (size_t)(t0 + slot) * NC + ks * DPART;
    const float* xB = xA + (size_t)8 * NC;

    ull acc[12];
#pragma unroll
    for (int k = 0; k < 12; ++k) acc[k] = 0ull;
    ull ssqA = 0ull, ssqB = 0ull;

    asm volatile("cp.async.wait_group 0;");
    __syncthreads();                              // the only barrier

    const float* pk = sphi + (kh * 6) * DPART;   // this thread's first k-row

    // software-pipelined x prefetch
    ulonglong2 xa = *(const ulonglong2*)(xA + s * 4);
    ulonglong2 xb = *(const ulonglong2*)(xB + s * 4);

#pragma unroll 4
    for (int j = 0; j < 16; ++j) {
        ulonglong2 na, nb;
        if (j < 15) {
            na = *(const ulonglong2*)(xA + (j + 1) * 32 + s * 4);
            nb = *(const ulonglong2*)(xB + (j + 1) * 32 + s * 4);
        }
        if (kh == 0) {
            ffma2(ssqA, xa.x, xa.x); ffma2(ssqA, xa.y, xa.y);
            ffma2(ssqB, xb.x, xb.x); ffma2(ssqB, xb.y, xb.y);
        }
        const float* pd = pk + j * 32 + s * 4;
#pragma unroll
        for (int c = 0; c < 6; ++c) {
            ulonglong2 p = *(const ulonglong2*)(pd + c * DPART);
            ffma2(acc[c],     xa.x, p.x); ffma2(acc[c],     xa.y, p.y);
            ffma2(acc[6 + c], xb.x, p.x); ffma2(acc[6 + c], xb.y, p.y);
        }
        xa = na; xb = nb;
    }

    // reduce over the 8 d-slices (lane bits 0..2)
#pragma unroll
    for (int k = 0; k < 12; ++k) {
#pragma unroll
        for (int m = 1; m < 8; m <<= 1) {
            ull o = __shfl_xor_sync(0xffffffffu, acc[k], m);
            fadd2(acc[k], acc[k], o);
        }
    }
    if (kh == 0) {
#pragma unroll
        for (int m = 1; m < 8; m <<= 1) {
            ull o = __shfl_xor_sync(0xffffffffu, ssqA, m);
            fadd2(ssqA, ssqA, o);
            o = __shfl_xor_sync(0xffffffffu, ssqB, m);
            fadd2(ssqB, ssqB, o);
        }
    }

    if (s == 0) {
        float* pa = part_buf + ((size_t)ks * (BB * TT) + t0 + slot) * PARTW;
        float* pb = part_buf + ((size_t)ks * (BB * TT) + t0 + slot + 8) * PARTW;
#pragma unroll
        for (int c = 0; c < 6; ++c) {
            float lo, hi;
            unpack2(acc[c], lo, hi);
            pa[kh * 6 + c] = lo + hi;            // genuine d-pairs: sum the halves
            unpack2(acc[6 + c], lo, hi);
            pb[kh * 6 + c] = lo + hi;
        }
        if (kh == 0) {
            float lo, hi;
            unpack2(ssqA, lo, hi);
            pa[24] = lo + hi;
            unpack2(ssqB, lo, hi);
            pb[24] = lo + hi;
        }
    }
}

// ---------------- kernel 3: finalize (reduce 8 splits, sinkhorn -> W) ----------------
// part layout per token: [k] at k (k = kh*6+c covers 0..23 exactly), ssq at [24]
__global__ void finalize_k(const float* __restrict__ bpre, const float* __restrict__ bpost,
                           const float* __restrict__ bres, const int* __restrict__ aidx) {
    const int t = blockIdx.x * 128 + threadIdx.x;
    const int aid = aidx[t >> 11];

    float a[24];
#pragma unroll
    for (int k = 0; k < 24; ++k) a[k] = 0.0f;
    float ssq = 0.0f;
#pragma unroll
    for (int ks = 0; ks < KSPLIT; ++ks) {
        const float4* p = (const float4*)(part_buf + ((size_t)ks * (BB * TT) + t) * PARTW);
#pragma unroll
        for (int q = 0; q < 6; ++q) {
            float4 v = p[q];
            a[q * 4 + 0] += v.x; a[q * 4 + 1] += v.y;
            a[q * 4 + 2] += v.z; a[q * 4 + 3] += v.w;
        }
        ssq += p[6].x;
    }
    float rinv = rsqrtf(ssq * (1.0f / 4096.0f) + EPS_);

    float hpre[4], hpost[4];
#pragma unroll
    for (int n = 0; n < 4; ++n)
        hpre[n] = 1.0f / (1.0f + expf(-(a[n] * rinv + bpre[aid * 4 + n])));
#pragma unroll
    for (int n = 0; n < 4; ++n)
        hpost[n] = 2.0f / (1.0f + expf(-(a[4 + n] * rinv + bpost[aid * 4 + n])));

    float m[16];
#pragma unroll
    for (int ij = 0; ij < 16; ++ij)
        m[ij] = expf(a[8 + ij] * rinv + bres[aid * 16 + ij]);

    for (int it = 0; it < SINK_ITERS; ++it) {
#pragma unroll
        for (int i = 0; i < 4; ++i) {
            float r = 1.0f / (m[i * 4] + m[i * 4 + 1] + m[i * 4 + 2] + m[i * 4 + 3]);
            m[i * 4] *= r; m[i * 4 + 1] *= r; m[i * 4 + 2] *= r; m[i * 4 + 3] *= r;
        }
#pragma unroll
        for (int j = 0; j < 4; ++j) {
            float r = 1.0f / (m[j] + m[4 + j] + m[8 + j] + m[12 + j]);
            m[j] *= r; m[4 + j] *= r; m[8 + j] *= r; m[12 + j] *= r;
        }
    }

    float4* wd = (float4*)(W_buf + (size_t)t * 16);
#pragma unroll
    for (int i = 0; i < 4; ++i)
        wd[i] = make_float4(m[i * 4 + 0] + hpost[i] * hpre[0],
                            m[i * 4 + 1] + hpost[i] * hpre[1],
                            m[i * 4 + 2] + hpost[i] * hpre[2],
                            m[i * 4 + 3] + hpost[i] * hpre[3]);
}

// ---------------- kernel 4: out[token] = W @ x[token] ----------------
__global__ void out_k(const float* __restrict__ x, float* __restrict__ out) {
    const int token = blockIdx.x;
    __shared__ float sW[16];
    if (threadIdx.x < 16) sW[threadIdx.x] = W_buf[(size_t)token * 16 + threadIdx.x];
    __syncthreads();
    const float4* xr = (const float4*)(x + (size_t)token * NC);
    float4* orow = (float4*)(out + (size_t)token * NC);
    const int c = threadIdx.x;
    float4 xv0 = xr[c], xv1 = xr[256 + c], xv2 = xr[512 + c], xv3 = xr[768 + c];
#pragma unroll
    for (int i = 0; i < 4; ++i) {
        float w0 = sW[i * 4], w1 = sW[i * 4 + 1], w2 = sW[i * 4 + 2], w3 = sW[i * 4 + 3];
        float4 o;
        o.x = w0 * xv0.x + w1 * xv1.x + w2 * xv2.x + w3 * xv3.x;
        o.y = w0 * xv0.y + w1 * xv1.y + w2 * xv2.y + w3 * xv3.y;
        o.z = w0 * xv0.z + w1 * xv1.z + w2 * xv2.z + w3 * xv3.z;
        o.w = w0 * xv0.w + w1 * xv1.w + w2 * xv2.w + w3 * xv3.w;
        orow[i * 256 + c] = o;
    }
}

// ---------------- launch ----------------
extern "C" void kernel_launch(void* const* d_in, const int* in_sizes, int n_in,
                              void* d_out, int out_size) {
    const float* x     = (const float*)d_in[0];
    const float* wnorm = (const float*)d_in[1];
    const float* ppre  = (const float*)d_in[2];
    const float* ppost = (const float*)d_in[3];
    const float* pres  = (const float*)d_in[4];
    const float* bpre  = (const float*)d_in[5];
    const float* bpost = (const float*)d_in[6];
    const float* bres  = (const float*)d_in[7];
    const float* apre  = (const float*)d_in[8];
    const float* apost = (const float*)d_in[9];
    const float* ares  = (const float*)d_in[10];
    const int*   aidx  = (const int*)d_in[11];
    float* out = (float*)d_out;

    fold_k<<<(AA * NC + 127) / 128, 128>>>(wnorm, ppre, ppost, pres, apre, apost, ares);
    logits_k<<<(BB * TT / TOK) * KSPLIT, NTHR>>>(x, aidx);
    finalize_k<<<BB * TT / 128, 128>>>(bpre, bpost, bres, aidx);
    out_k<<<BB * TT, 256>>>(x, out);
}

// round 11
// speedup vs baseline: 1.2871x; 1.2871x over previous
#include <cuda_runtime.h>
#include <cstdint>

// Problem constants
#define BB   4
#define TT   2048
#define NC   4096
#define AA   8
#define SINK_ITERS 20
#define EPS_ 1e-5f

// logits tiling (identical to the best-measured R3 config)
#define TOK    32            // tokens per CTA
#define DT     128           // d-tile
#define KSPLIT 8
#define DPART  (NC / KSPLIT) // 512
#define TILES  (DPART / DT)  // 4
#define XROWF  136           // x smem row stride (floats)
#define PROWF  28            // phi smem row stride (floats)
#define PARTW  28            // partial row: 24 logits + ssq + pad

#define XT (TOK * XROWF)     // 4352 floats
#define PT (DT * PROWF)      // 3584 floats
#define BUFF (XT + PT)       // 7936 floats
#define SMEM_BYTES (2 * BUFF * 4)

// ---------------- scratch ----------------
__device__ __align__(16) float g_buf[AA * NC * 24];                 // folded phi [a][d][24]
__device__ __align__(16) float part_buf[KSPLIT * BB * TT * PARTW];  // 7.3 MB
__device__ __align__(16) float W_buf[BB * TT * 16];

// ---------------- helpers ----------------
typedef unsigned long long ull;
__device__ __forceinline__ void ffma2(ull& d, ull a, ull b) {
    asm("fma.rn.f32x2 %0, %1, %2, %0;" : "+l"(d) : "l"(a), "l"(b));
}
__device__ __forceinline__ void fadd2(ull& d, ull a, ull b) {
    asm("add.rn.f32x2 %0, %1, %2;" : "=l"(d) : "l"(a), "l"(b));
}
__device__ __forceinline__ ull dup2(float v) {
    ull r; asm("mov.b64 %0, {%1, %1};" : "=l"(r) : "f"(v)); return r;
}
__device__ __forceinline__ void unpack2(ull u, float& lo, float& hi) {
    asm("mov.b64 {%0, %1}, %2;" : "=f"(lo), "=f"(hi) : "l"(u));
}
__device__ __forceinline__ void cp16(uint32_t dst, const void* src) {
    asm volatile("cp.async.cg.shared.global [%0], [%1], 16;" :: "r"(dst), "l"(src));
}

// ---------------- kernel 1: fold alpha*w*phi -> g_buf[a][d][24] (fast, coalesced) ----------------
__global__ void fold_k(const float* __restrict__ wnorm,
                       const float* __restrict__ ppre, const float* __restrict__ ppost,
                       const float* __restrict__ pres,
                       const float* __restrict__ apre, const float* __restrict__ apost,
                       const float* __restrict__ ares) {
    int idx = blockIdx.x * 256 + threadIdx.x;    // (a,d)*6 + c
    if (idx >= AA * NC * 6) return;
    int c = idx % 6;
    int ad = idx / 6;
    int a = ad >> 12;
    float wv = wnorm[ad];
    float coef = ((c == 0) ? apre[a] : (c == 1) ? apost[a] : ares[a]) * wv;
    float4 v = (c == 0) ? ((const float4*)ppre)[ad]
             : (c == 1) ? ((const float4*)ppost)[ad]
                        : ((const float4*)pres)[(size_t)ad * 4 + (c - 2)];
    ((float4*)g_buf)[idx] = make_float4(coef * v.x, coef * v.y, coef * v.z, coef * v.w);
}

// ---------------- kernel 2: partial logits (R3 exact) ----------------
// grid = 2048: blockIdx.x = tt*KSPLIT + ks. 128 threads:
//   s = tid&7 (d-slice), tg = (tid>>3)&7 (token group: tokens tg+8j), kh = tid>>6 (k half)
__global__ void __launch_bounds__(128, 3)
logits_k(const float* __restrict__ x, const int* __restrict__ aidx) {
    extern __shared__ float smem[];
    const int tid = threadIdx.x;
    const int ks = blockIdx.x & (KSPLIT - 1);
    const int tt = blockIdx.x >> 3;
    const int b  = tt >> 6;
    const int t0 = (tt & 63) * TOK;
    const int aid = aidx[b];
    const int s = tid & 7, tg = (tid >> 3) & 7, kh = tid >> 6;

    const float* xb = x + ((size_t)(b * TT + t0)) * NC + ks * DPART;
    const float* gb = g_buf + ((size_t)aid * NC + ks * DPART) * 24;

    uint32_t sbase = (uint32_t)__cvta_generic_to_shared(smem);
    const uint32_t xbase[2] = { sbase,          sbase + BUFF * 4 };
    const uint32_t pbase[2] = { sbase + XT * 4, sbase + (BUFF + XT) * 4 };

    ull acc[24];
#pragma unroll
    for (int k = 0; k < 24; ++k) acc[k] = 0ull;
    ull ssq[4] = {0ull, 0ull, 0ull, 0ull};

    auto copy_tile = [&](int tile, int bi) {
        const int d0 = tile * DT;
#pragma unroll
        for (int i2 = 0; i2 < 8; ++i2) {            // x: 1024 float4
            int f = i2 * 128 + tid;
            int tok = f >> 5, q = f & 31;
            cp16(xbase[bi] + tok * (XROWF * 4) + q * 16,
                 xb + (size_t)tok * NC + d0 + q * 4);
        }
#pragma unroll
        for (int i2 = 0; i2 < 6; ++i2) {            // phi: 768 float4
            int f = i2 * 128 + tid;
            int d = f / 6, c = f - d * 6;
            cp16(pbase[bi] + d * (PROWF * 4) + c * 16,
                 gb + (size_t)(d0 + d) * 24 + c * 4);
        }
        asm volatile("cp.async.commit_group;");
    };

    copy_tile(0, 0);

    for (int t = 0; t < TILES; ++t) {
        if (t + 1 < TILES) {
            copy_tile(t + 1, (t + 1) & 1);
            asm volatile("cp.async.wait_group 1;");
        } else {
            asm volatile("cp.async.wait_group 0;");
        }
        __syncthreads();

        const float* xs = smem + (t & 1) * BUFF;
        const float* ps = xs + XT;
        const float* xr0 = xs + (tg     ) * XROWF;
        const float* xr1 = xs + (tg +  8) * XROWF;
        const float* xr2 = xs + (tg + 16) * XROWF;
        const float* xr3 = xs + (tg + 24) * XROWF;

#pragma unroll 4
        for (int i = 0; i < 16; ++i) {
            const int dd = i * 8 + s;
            ull x0 = dup2(xr0[dd]);
            ull x1 = dup2(xr1[dd]);
            ull x2 = dup2(xr2[dd]);
            ull x3 = dup2(xr3[dd]);
            if (kh == 0) {
                ffma2(ssq[0], x0, x0); ffma2(ssq[1], x1, x1);
                ffma2(ssq[2], x2, x2); ffma2(ssq[3], x3, x3);
            }
            const ulonglong2* pp = (const ulonglong2*)(ps + dd * PROWF + kh * 12);
            ulonglong2 pA = pp[0], pB = pp[1], pC = pp[2];
            ffma2(acc[0],  x0, pA.x); ffma2(acc[6],  x1, pA.x);
            ffma2(acc[12], x2, pA.x); ffma2(acc[18], x3, pA.x);
            ffma2(acc[1],  x0, pA.y); ffma2(acc[7],  x1, pA.y);
            ffma2(acc[13], x2, pA.y); ffma2(acc[19], x3, pA.y);
            ffma2(acc[2],  x0, pB.x); ffma2(acc[8],  x1, pB.x);
            ffma2(acc[14], x2, pB.x); ffma2(acc[20], x3, pB.x);
            ffma2(acc[3],  x0, pB.y); ffma2(acc[9],  x1, pB.y);
            ffma2(acc[15], x2, pB.y); ffma2(acc[21], x3, pB.y);
            ffma2(acc[4],  x0, pC.x); ffma2(acc[10], x1, pC.x);
            ffma2(acc[16], x2, pC.x); ffma2(acc[22], x3, pC.x);
            ffma2(acc[5],  x0, pC.y); ffma2(acc[11], x1, pC.y);
            ffma2(acc[17], x2, pC.y); ffma2(acc[23], x3, pC.y);
        }
        __syncthreads();
    }

    // reduce over the 8 d-slices (lane bits 0..2)
#pragma unroll
    for (int k = 0; k < 24; ++k) {
#pragma unroll
        for (int m = 1; m < 8; m <<= 1) {
            ull o = __shfl_xor_sync(0xffffffffu, acc[k], m);
            fadd2(acc[k], acc[k], o);
        }
    }
    if (kh == 0) {
#pragma unroll
        for (int j = 0; j < 4; ++j) {
#pragma unroll
            for (int m = 1; m < 8; m <<= 1) {
                ull o = __shfl_xor_sync(0xffffffffu, ssq[j], m);
                fadd2(ssq[j], ssq[j], o);
            }
        }
    }

    if (s == 0) {
        const int tbase = b * TT + t0 + tg;
#pragma unroll
        for (int j = 0; j < 4; ++j) {
            float* pa = part_buf + ((size_t)ks * (BB * TT) + tbase + 8 * j) * PARTW;
#pragma unroll
            for (int c = 0; c < 6; ++c) {
                float lo, hi; unpack2(acc[j * 6 + c], lo, hi);
                pa[kh * 12 + 2 * c]     = lo;
                pa[kh * 12 + 2 * c + 1] = hi;
            }
            if (kh == 0) {
                float lo, hi; unpack2(ssq[j], lo, hi);
                pa[24] = lo;   // duplicated lanes: lo == hi == true sum
            }
        }
    }
}

// ---------------- kernel 3: finalize (reduce splits, sinkhorn -> W) ----------------
__global__ void finalize_k(const float* __restrict__ bpre, const float* __restrict__ bpost,
                           const float* __restrict__ bres, const int* __restrict__ aidx) {
    const int t = blockIdx.x * 128 + threadIdx.x;
    const int aid = aidx[t >> 11];

    float a[24];
#pragma unroll
    for (int k = 0; k < 24; ++k) a[k] = 0.0f;
    float ssq = 0.0f;
#pragma unroll
    for (int ks = 0; ks < KSPLIT; ++ks) {
        const float4* p = (const float4*)(part_buf + ((size_t)ks * (BB * TT) + t) * PARTW);
#pragma unroll
        for (int q = 0; q < 6; ++q) {
            float4 v = p[q];
            a[q * 4 + 0] += v.x; a[q * 4 + 1] += v.y;
            a[q * 4 + 2] += v.z; a[q * 4 + 3] += v.w;
        }
        ssq += p[6].x;
    }
    float rinv = rsqrtf(ssq * (1.0f / 4096.0f) + EPS_);

    float hpre[4], hpost[4];
#pragma unroll
    for (int n = 0; n < 4; ++n)
        hpre[n] = 1.0f / (1.0f + expf(-(a[n] * rinv + bpre[aid * 4 + n])));
#pragma unroll
    for (int n = 0; n < 4; ++n)
        hpost[n] = 2.0f / (1.0f + expf(-(a[4 + n] * rinv + bpost[aid * 4 + n])));

    float m[16];
#pragma unroll
    for (int ij = 0; ij < 16; ++ij)
        m[ij] = expf(a[8 + ij] * rinv + bres[aid * 16 + ij]);

    for (int it = 0; it < SINK_ITERS; ++it) {
#pragma unroll
        for (int i = 0; i < 4; ++i) {
            float r = 1.0f / (m[i * 4] + m[i * 4 + 1] + m[i * 4 + 2] + m[i * 4 + 3]);
            m[i * 4] *= r; m[i * 4 + 1] *= r; m[i * 4 + 2] *= r; m[i * 4 + 3] *= r;
        }
#pragma unroll
        for (int j = 0; j < 4; ++j) {
            float r = 1.0f / (m[j] + m[4 + j] + m[8 + j] + m[12 + j]);
            m[j] *= r; m[4 + j] *= r; m[8 + j] *= r; m[12 + j] *= r;
        }
    }

    float4* wd = (float4*)(W_buf + (size_t)t * 16);
#pragma unroll
    for (int i = 0; i < 4; ++i)
        wd[i] = make_float4(m[i * 4 + 0] + hpost[i] * hpre[0],
                            m[i * 4 + 1] + hpost[i] * hpre[1],
                            m[i * 4 + 2] + hpost[i] * hpre[2],
                            m[i * 4 + 3] + hpost[i] * hpre[3]);
}

// ---------------- kernel 4: out[token] = W @ x[token], REVERSED order for L2 x reuse ----------------
// logits_k streamed x forward; reversing makes the first out_k waves hit the x
// tokens most recently resident in L2.
__global__ void out_k(const float* __restrict__ x, float* __restrict__ out) {
    const int token = (BB * TT - 1) - blockIdx.x;
    __shared__ float sW[16];
    if (threadIdx.x < 16) sW[threadIdx.x] = W_buf[(size_t)token * 16 + threadIdx.x];
    __syncthreads();
    const float4* xr = (const float4*)(x + (size_t)token * NC);
    float4* orow = (float4*)(out + (size_t)token * NC);
    const int c = threadIdx.x;
    float4 xv0 = xr[c], xv1 = xr[256 + c], xv2 = xr[512 + c], xv3 = xr[768 + c];
#pragma unroll
    for (int i = 0; i < 4; ++i) {
        float w0 = sW[i * 4], w1 = sW[i * 4 + 1], w2 = sW[i * 4 + 2], w3 = sW[i * 4 + 3];
        float4 o;
        o.x = w0 * xv0.x + w1 * xv1.x + w2 * xv2.x + w3 * xv3.x;
        o.y = w0 * xv0.y + w1 * xv1.y + w2 * xv2.y + w3 * xv3.y;
        o.z = w0 * xv0.z + w1 * xv1.z + w2 * xv2.z + w3 * xv3.z;
        o.w = w0 * xv0.w + w1 * xv1.w + w2 * xv2.w + w3 * xv3.w;
        orow[i * 256 + c] = o;
    }
}

// ---------------- launch ----------------
extern "C" void kernel_launch(void* const* d_in, const int* in_sizes, int n_in,
                              void* d_out, int out_size) {
    const float* x     = (const float*)d_in[0];
    const float* wnorm = (const float*)d_in[1];
    const float* ppre  = (const float*)d_in[2];
    const float* ppost = (const float*)d_in[3];
    const float* pres  = (const float*)d_in[4];
    const float* bpre  = (const float*)d_in[5];
    const float* bpost = (const float*)d_in[6];
    const float* bres  = (const float*)d_in[7];
    const float* apre  = (const float*)d_in[8];
    const float* apost = (const float*)d_in[9];
    const float* ares  = (const float*)d_in[10];
    const int*   aidx  = (const int*)d_in[11];
    float* out = (float*)d_out;

    cudaFuncSetAttribute(logits_k, cudaFuncAttributeMaxDynamicSharedMemorySize, SMEM_BYTES);

    fold_k<<<(AA * NC * 6 + 255) / 256, 256>>>(wnorm, ppre, ppost, pres, apre, apost, ares);
    logits_k<<<(BB * TT / TOK) * KSPLIT, 128, SMEM_BYTES>>>(x, aidx);
    finalize_k<<<BB * TT / 128, 128>>>(bpre, bpost, bres, aidx);
    out_k<<<BB * TT, 256>>>(x, out);
}